// round 15
// baseline (speedup 1.0000x reference)
#include <cuda_runtime.h>
#include <cuda_fp16.h>
#include <cstdint>

#define M_ 16384
#define N_ 3072
#define K_ 1024

// -------- device scratch (allowed: __device__ globals) --------
__device__ float  g_qkv[(size_t)M_ * N_];      // 192 MB
__device__ __half g_Ah[(size_t)M_ * K_];       // 32 MB  x fp16   [M,K]
__device__ __half g_Bh[(size_t)N_ * K_];       // 6 MB   W^T fp16 [N,K]

// ---------------------------------------------------------------------------
// Pre-kernel 1: convert x -> fp16, same [M,K] layout.
// ---------------------------------------------------------------------------
__global__ __launch_bounds__(256) void split_x_kernel(const float* __restrict__ x)
{
    size_t idx = (size_t)blockIdx.x * 256 + threadIdx.x;    // float4 index
    float4 v = ((const float4*)x)[idx];
    ((__half2*)g_Ah)[2 * idx]     = __halves2half2(__float2half_rn(v.x), __float2half_rn(v.y));
    ((__half2*)g_Ah)[2 * idx + 1] = __halves2half2(__float2half_rn(v.z), __float2half_rn(v.w));
}

// ---------------------------------------------------------------------------
// Pre-kernel 2: transpose W [K,N] -> g_Bh fp16 [N,K].
// ---------------------------------------------------------------------------
__global__ __launch_bounds__(256) void split_w_kernel(const float* __restrict__ W)
{
    __shared__ float t[32][33];
    const int k0 = blockIdx.x * 32;
    const int n0 = blockIdx.y * 32;
    const int tid = threadIdx.x;
    #pragma unroll
    for (int i = 0; i < 4; i++) {
        int idx = tid + i * 256;
        int r = idx >> 5, c = idx & 31;
        t[r][c] = W[(size_t)(k0 + r) * N_ + n0 + c];
    }
    __syncthreads();
    #pragma unroll
    for (int i = 0; i < 4; i++) {
        int idx = tid + i * 256;
        int r = idx >> 5, c = idx & 31;
        g_Bh[(size_t)(n0 + r) * K_ + k0 + c] = __float2half_rn(t[c][r]);
    }
}

// ---------------------------------------------------------------------------
// Main GEMM: qkv = x @ W + b via mma.sync.m16n8k16 fp16, single pass, f32 acc.
// CTA 128x128, 8 warps (2x4), warp tile 64x32, KC=64 (8 chunks -> half the
// barrier/wait overhead vs KC=32), 2-stage cp.async. Rows 128B payload,
// ROWB=144 (stride 36 words == 4 mod 32: ldmatrix stays conflict-free).
// ---------------------------------------------------------------------------
#define KC 64
#define ROWB 144
#define TILE_BYTES (128 * ROWB)            // 18432
#define STG_BYTES (2 * TILE_BYTES)         // A, B = 36864
#define SMEM_TOTAL (2 * STG_BYTES)         // 73728

__device__ __forceinline__ uint32_t cvta_smem(const void* p) {
    uint32_t a;
    asm("{ .reg .u64 t; cvta.to.shared.u64 t, %1; cvt.u32.u64 %0, t; }"
        : "=r"(a) : "l"(p));
    return a;
}

#define CP16(dst, src) \
    asm volatile("cp.async.cg.shared.global [%0], [%1], 16;" \
                 :: "r"(dst), "l"(src) : "memory")

#define LDSM4(r, addr) \
    asm volatile("ldmatrix.sync.aligned.m8n8.x4.shared.b16 {%0,%1,%2,%3}, [%4];" \
                 : "=r"((r)[0]), "=r"((r)[1]), "=r"((r)[2]), "=r"((r)[3]) \
                 : "r"(addr))

#define MMAF32(c, a, b0, b1) \
    asm volatile("mma.sync.aligned.m16n8k16.row.col.f32.f16.f16.f32 " \
                 "{%0,%1,%2,%3}, {%4,%5,%6,%7}, {%8,%9}, {%0,%1,%2,%3};" \
                 : "+f"((c)[0]), "+f"((c)[1]), "+f"((c)[2]), "+f"((c)[3]) \
                 : "r"((a)[0]), "r"((a)[1]), "r"((a)[2]), "r"((a)[3]), \
                   "r"(b0), "r"(b1))

__global__ __launch_bounds__(256) void gemm_fp16_kernel(const float* __restrict__ bias)
{
    extern __shared__ __align__(128) char smem[];
    const uint32_t sb = cvta_smem(smem);

    const int tid  = threadIdx.x;
    const int wid  = tid >> 5;
    const int lane = tid & 31;
    const int wm   = wid >> 2;          // 0..1 (M)
    const int wn   = wid & 3;           // 0..3 (N)
    const int n0 = blockIdx.x * 128;
    const int m0 = blockIdx.y * 128;

    // cp.async: 128 rows x 128B per tile; 2 threads/row, 4 CP16 each.
    const int row = tid >> 1;            // 0..127
    const int cb  = (tid & 1) * 64;      // byte offset within 128B payload

    float acc[4][4][4];
    #pragma unroll
    for (int i = 0; i < 4; i++)
        #pragma unroll
        for (int j = 0; j < 4; j++)
            #pragma unroll
            for (int q = 0; q < 4; q++) acc[i][j][q] = 0.0f;

    #define LOAD_STAGE(s, c)  do {                                              \
        uint32_t db = sb + (s) * STG_BYTES;                                     \
        int k0 = (c) * KC;                                                      \
        const char* ga = (const char*)(g_Ah + (size_t)(m0 + row) * K_ + k0) + cb; \
        const char* gb = (const char*)(g_Bh + (size_t)(n0 + row) * K_ + k0) + cb; \
        uint32_t da = db + row * ROWB + cb;                                     \
        _Pragma("unroll")                                                       \
        for (int i = 0; i < 4; i++) {                                           \
            CP16(da + i * 16, ga + i * 16);                                     \
            CP16(da + TILE_BYTES + i * 16, gb + i * 16);                        \
        }                                                                       \
        asm volatile("cp.async.commit_group;" ::: "memory");                    \
    } while (0)

    LOAD_STAGE(0, 0);

    const int rA = wm * 64 + ((lane >> 3) & 1) * 8 + (lane & 7);
    const int cA = ((lane >> 4) & 1) * 8;                  // + kk*16
    const int rB = wn * 32 + ((lane >> 4) & 1) * 8 + (lane & 7);
    const int cB = ((lane >> 3) & 1) * 8;                  // + kk*16

    const int NCH = K_ / KC;               // 8
    for (int c = 0; c < NCH; c++) {
        if (c + 1 < NCH) {
            LOAD_STAGE((c + 1) & 1, c + 1);
            asm volatile("cp.async.wait_group 1;" ::: "memory");
        } else {
            asm volatile("cp.async.wait_group 0;" ::: "memory");
        }
        __syncthreads();

        const uint32_t st = sb + (c & 1) * STG_BYTES;
        #pragma unroll
        for (int kk = 0; kk < 4; kk++) {
            uint32_t a_f[4][4], b_f[2][4];
            #pragma unroll
            for (int mi = 0; mi < 4; mi++) {
                uint32_t ad = st + (rA + mi * 16) * ROWB + (cA + kk * 16) * 2;
                LDSM4(a_f[mi], ad);
            }
            #pragma unroll
            for (int ni = 0; ni < 2; ni++) {
                uint32_t bd = st + TILE_BYTES +
                              (rB + ni * 16) * ROWB + (cB + kk * 16) * 2;
                LDSM4(b_f[ni], bd);
            }
            #pragma unroll
            for (int mi = 0; mi < 4; mi++)
                #pragma unroll
                for (int nj = 0; nj < 4; nj++)
                    MMAF32(acc[mi][nj], a_f[mi],
                           b_f[nj >> 1][(nj & 1) * 2], b_f[nj >> 1][(nj & 1) * 2 + 1]);
        }
        __syncthreads();
    }

    // ---- epilogue: bias + store f32 ----
    #pragma unroll
    for (int mi = 0; mi < 4; mi++) {
        #pragma unroll
        for (int nj = 0; nj < 4; nj++) {
            int orow = m0 + wm * 64 + mi * 16 + (lane >> 2);
            int ocol = n0 + wn * 32 + nj * 8 + (lane & 3) * 2;
            float2 bv = *(const float2*)(bias + ocol);
            float2 v0, v1;
            v0.x = acc[mi][nj][0] + bv.x;
            v0.y = acc[mi][nj][1] + bv.y;
            v1.x = acc[mi][nj][2] + bv.x;
            v1.y = acc[mi][nj][3] + bv.y;
            *(float2*)(g_qkv + (size_t)orow * N_ + ocol)       = v0;
            *(float2*)(g_qkv + (size_t)(orow + 8) * N_ + ocol) = v1;
        }
    }
}

// ---------------------------------------------------------------------------
// Attention kernel. 2x2-blocked score pass (64 threads, 4 dots/thread:
// halves score LDS wavefronts) and 2-output V pass (shared V loads:
// halves V wavefronts). Same math order -> bit-identical to R5 version.
// ---------------------------------------------------------------------------
#define HSTR 196                         // padded per-head stride (floats)
#define HSTR4 49                         // float4 stride

__global__ __launch_bounds__(256, 4) void attn_kernel(float* __restrict__ out)
{
    __shared__ __align__(16) float qkv[16 * HSTR];   // 12.25 KB
    __shared__ float E[256];
    __shared__ float invden[16];

    const int token = blockIdx.x;
    const int tid   = threadIdx.x;

    // Stage token row (768 float4) into padded layout: 48 float4 per head.
    const float4* row4 = (const float4*)(g_qkv + (size_t)token * N_);
    #pragma unroll
    for (int r = 0; r < 3; r++) {
        int i = tid + r * 256;
        int head = i / 48;
        int w    = i - head * 48;
        ((float4*)qkv)[head * HSTR4 + w] = row4[i];
    }
    __syncthreads();

    // Scores: 64 threads, each computes the 2x2 block (h8,h8+8)x(g8,g8+8).
    if (tid < 64) {
        const int h8 = tid >> 3;         // 0..7
        const int g8 = tid & 7;          // 0..7
        const float* q0 = &qkv[h8 * HSTR];
        const float* q1 = &qkv[(h8 + 8) * HSTR];
        const float* k0 = &qkv[g8 * HSTR + 64];
        const float* k1 = &qkv[(g8 + 8) * HSTR + 64];
        float s00 = 0.f, s01 = 0.f, s10 = 0.f, s11 = 0.f;
        #pragma unroll
        for (int d = 0; d < 64; d++) {
            float qa = q0[d], qb = q1[d];
            float ka = k0[d], kb = k1[d];
            s00 = fmaf(qa, ka, s00);
            s01 = fmaf(qa, kb, s01);
            s10 = fmaf(qb, ka, s10);
            s11 = fmaf(qb, kb, s11);
        }
        s00 -= 20.0f; s01 -= 20.0f; s10 -= 20.0f; s11 -= 20.0f;
        E[h8 * 16 + g8]            = (s00 > 20.f || s00 < -20.f) ? 0.f : expf(s00);
        E[h8 * 16 + g8 + 8]        = (s01 > 20.f || s01 < -20.f) ? 0.f : expf(s01);
        E[(h8 + 8) * 16 + g8]      = (s10 > 20.f || s10 < -20.f) ? 0.f : expf(s10);
        E[(h8 + 8) * 16 + g8 + 8]  = (s11 > 20.f || s11 < -20.f) ? 0.f : expf(s11);
    }
    __syncthreads();

    if (tid < 16) {
        float den = 0.0f;
        #pragma unroll
        for (int gg = 0; gg < 16; gg++) den += E[tid * 16 + gg];
        invden[tid] = 1.0f / den;
    }
    __syncthreads();

    // V pass: 2 rounds; each thread produces (hh8, hh8+8) sharing V loads.
    float* o = out + (size_t)token * 1024;
    #pragma unroll
    for (int r = 0; r < 2; r++) {
        int idx = tid + r * 256;          // 0..511
        int hh8 = idx >> 6;               // 0..7
        int d   = idx & 63;
        float a0 = 0.0f, a1 = 0.0f;
        const float* E0 = &E[hh8 * 16];
        const float* E1 = &E[(hh8 + 8) * 16];
        #pragma unroll
        for (int gg = 0; gg < 16; gg++) {
            float v = qkv[gg * HSTR + 128 + d];
            a0 = fmaf(E0[gg], v, a0);
            a1 = fmaf(E1[gg], v, a1);
        }
        o[hh8 * 64 + d]       = a0 * invden[hh8];
        o[(hh8 + 8) * 64 + d] = a1 * invden[hh8 + 8];
    }
}

// ---------------------------------------------------------------------------
extern "C" void kernel_launch(void* const* d_in, const int* in_sizes, int n_in,
                              void* d_out, int out_size)
{
    const float* x = (const float*)d_in[0];
    const float* W = (const float*)d_in[1];
    const float* b = (const float*)d_in[2];
    float* out = (float*)d_out;

    cudaFuncSetAttribute(gemm_fp16_kernel,
                         cudaFuncAttributeMaxDynamicSharedMemorySize, SMEM_TOTAL);

    split_x_kernel<<<(M_ * K_) / (256 * 4), 256>>>(x);
    split_w_kernel<<<dim3(K_ / 32, N_ / 32), 256>>>(W);
    gemm_fp16_kernel<<<dim3(N_ / 128, M_ / 128), 256, SMEM_TOTAL>>>(b);
    attn_kernel<<<M_, 256>>>(out);
}

// round 16
// speedup vs baseline: 1.2144x; 1.2144x over previous
#include <cuda_runtime.h>
#include <cuda_fp16.h>
#include <cstdint>

#define M_ 16384
#define N_ 3072
#define K_ 1024

// -------- device scratch (allowed: __device__ globals) --------
__device__ float  g_qkv[(size_t)M_ * N_];      // 192 MB
__device__ __half g_Ah[(size_t)M_ * K_];       // 32 MB  x fp16   [M,K]
__device__ __half g_Bh[(size_t)N_ * K_];       // 6 MB   W^T fp16 [N,K]

// ---------------------------------------------------------------------------
// Pre-kernel 1: convert x -> fp16, same [M,K] layout.
// ---------------------------------------------------------------------------
__global__ __launch_bounds__(256) void split_x_kernel(const float* __restrict__ x)
{
    size_t idx = (size_t)blockIdx.x * 256 + threadIdx.x;    // float4 index
    float4 v = ((const float4*)x)[idx];
    ((__half2*)g_Ah)[2 * idx]     = __halves2half2(__float2half_rn(v.x), __float2half_rn(v.y));
    ((__half2*)g_Ah)[2 * idx + 1] = __halves2half2(__float2half_rn(v.z), __float2half_rn(v.w));
}

// ---------------------------------------------------------------------------
// Pre-kernel 2: transpose W [K,N] -> g_Bh fp16 [N,K].
// ---------------------------------------------------------------------------
__global__ __launch_bounds__(256) void split_w_kernel(const float* __restrict__ W)
{
    __shared__ float t[32][33];
    const int k0 = blockIdx.x * 32;
    const int n0 = blockIdx.y * 32;
    const int tid = threadIdx.x;
    #pragma unroll
    for (int i = 0; i < 4; i++) {
        int idx = tid + i * 256;
        int r = idx >> 5, c = idx & 31;
        t[r][c] = W[(size_t)(k0 + r) * N_ + n0 + c];
    }
    __syncthreads();
    #pragma unroll
    for (int i = 0; i < 4; i++) {
        int idx = tid + i * 256;
        int r = idx >> 5, c = idx & 31;
        g_Bh[(size_t)(n0 + r) * K_ + k0 + c] = __float2half_rn(t[c][r]);
    }
}

// ---------------------------------------------------------------------------
// Main GEMM: EXACT R14 configuration (best measured GEMM: ~350us).
// mma.sync.m16n8k16 fp16, single pass, f32 acc. CTA 128x128, 8 warps (2x4),
// warp tile 64x32, KC=32, ROWB=80, 2-stage cp.async.
// ---------------------------------------------------------------------------
#define KC 32
#define ASTRIDE 40
#define ROWB (ASTRIDE * 2)                 // 80 bytes per smem row
#define TILE_BYTES (128 * ROWB)            // 10240
#define STG_BYTES (2 * TILE_BYTES)         // A, B = 20480
#define SMEM_TOTAL (2 * STG_BYTES)         // 40960

__device__ __forceinline__ uint32_t cvta_smem(const void* p) {
    uint32_t a;
    asm("{ .reg .u64 t; cvta.to.shared.u64 t, %1; cvt.u32.u64 %0, t; }"
        : "=r"(a) : "l"(p));
    return a;
}

#define CP16(dst, src) \
    asm volatile("cp.async.cg.shared.global [%0], [%1], 16;" \
                 :: "r"(dst), "l"(src) : "memory")

#define LDSM4(r, addr) \
    asm volatile("ldmatrix.sync.aligned.m8n8.x4.shared.b16 {%0,%1,%2,%3}, [%4];" \
                 : "=r"((r)[0]), "=r"((r)[1]), "=r"((r)[2]), "=r"((r)[3]) \
                 : "r"(addr))

#define MMAF32(c, a, b0, b1) \
    asm volatile("mma.sync.aligned.m16n8k16.row.col.f32.f16.f16.f32 " \
                 "{%0,%1,%2,%3}, {%4,%5,%6,%7}, {%8,%9}, {%0,%1,%2,%3};" \
                 : "+f"((c)[0]), "+f"((c)[1]), "+f"((c)[2]), "+f"((c)[3]) \
                 : "r"((a)[0]), "r"((a)[1]), "r"((a)[2]), "r"((a)[3]), \
                   "r"(b0), "r"(b1))

__global__ __launch_bounds__(256) void gemm_fp16_kernel(const float* __restrict__ bias)
{
    extern __shared__ __align__(128) char smem[];
    const uint32_t sb = cvta_smem(smem);

    const int tid  = threadIdx.x;
    const int wid  = tid >> 5;
    const int lane = tid & 31;
    const int wm   = wid >> 2;          // 0..1 (M)
    const int wn   = wid & 3;           // 0..3 (N)
    const int n0 = blockIdx.x * 128;
    const int m0 = blockIdx.y * 128;

    const int r0 = tid >> 2;            // rows 0..63
    const int r1 = r0 + 64;             // rows 64..127
    const int c16 = (tid & 3) * 16;     // byte offset within 64B row payload

    float acc[4][4][4];
    #pragma unroll
    for (int i = 0; i < 4; i++)
        #pragma unroll
        for (int j = 0; j < 4; j++)
            #pragma unroll
            for (int q = 0; q < 4; q++) acc[i][j][q] = 0.0f;

    #define LOAD_STAGE(s, c)  do {                                              \
        uint32_t db = sb + (s) * STG_BYTES;                                     \
        int k0 = (c) * KC;                                                      \
        const char* a0 = (const char*)(g_Ah + (size_t)(m0 + r0) * K_ + k0) + c16; \
        const char* a1 = (const char*)(g_Ah + (size_t)(m0 + r1) * K_ + k0) + c16; \
        const char* b0 = (const char*)(g_Bh + (size_t)(n0 + r0) * K_ + k0) + c16; \
        const char* b1 = (const char*)(g_Bh + (size_t)(n0 + r1) * K_ + k0) + c16; \
        uint32_t d0 = db + r0 * ROWB + c16;                                     \
        uint32_t d1 = db + r1 * ROWB + c16;                                     \
        CP16(d0, a0);                     CP16(d1, a1);                         \
        CP16(d0 + TILE_BYTES, b0);        CP16(d1 + TILE_BYTES, b1);            \
        asm volatile("cp.async.commit_group;" ::: "memory");                    \
    } while (0)

    LOAD_STAGE(0, 0);

    const int rA = wm * 64 + ((lane >> 3) & 1) * 8 + (lane & 7);
    const int cA = ((lane >> 4) & 1) * 8;                  // + kk*16
    const int rB = wn * 32 + ((lane >> 4) & 1) * 8 + (lane & 7);
    const int cB = ((lane >> 3) & 1) * 8;                  // + kk*16

    const int NCH = K_ / KC;
    for (int c = 0; c < NCH; c++) {
        if (c + 1 < NCH) {
            LOAD_STAGE((c + 1) & 1, c + 1);
            asm volatile("cp.async.wait_group 1;" ::: "memory");
        } else {
            asm volatile("cp.async.wait_group 0;" ::: "memory");
        }
        __syncthreads();

        const uint32_t st = sb + (c & 1) * STG_BYTES;
        #pragma unroll
        for (int kk = 0; kk < 2; kk++) {
            uint32_t a_f[4][4], b_f[2][4];
            #pragma unroll
            for (int mi = 0; mi < 4; mi++) {
                uint32_t ad = st + (rA + mi * 16) * ROWB + (cA + kk * 16) * 2;
                LDSM4(a_f[mi], ad);
            }
            #pragma unroll
            for (int ni = 0; ni < 2; ni++) {
                uint32_t bd = st + TILE_BYTES +
                              (rB + ni * 16) * ROWB + (cB + kk * 16) * 2;
                LDSM4(b_f[ni], bd);
            }
            #pragma unroll
            for (int mi = 0; mi < 4; mi++)
                #pragma unroll
                for (int nj = 0; nj < 4; nj++)
                    MMAF32(acc[mi][nj], a_f[mi],
                           b_f[nj >> 1][(nj & 1) * 2], b_f[nj >> 1][(nj & 1) * 2 + 1]);
        }
        __syncthreads();
    }

    // ---- epilogue: bias + store f32 ----
    #pragma unroll
    for (int mi = 0; mi < 4; mi++) {
        #pragma unroll
        for (int nj = 0; nj < 4; nj++) {
            int orow = m0 + wm * 64 + mi * 16 + (lane >> 2);
            int ocol = n0 + wn * 32 + nj * 8 + (lane & 3) * 2;
            float2 bv = *(const float2*)(bias + ocol);
            float2 v0, v1;
            v0.x = acc[mi][nj][0] + bv.x;
            v0.y = acc[mi][nj][1] + bv.y;
            v1.x = acc[mi][nj][2] + bv.x;
            v1.y = acc[mi][nj][3] + bv.y;
            *(float2*)(g_qkv + (size_t)orow * N_ + ocol)       = v0;
            *(float2*)(g_qkv + (size_t)(orow + 8) * N_ + ocol) = v1;
        }
    }
}

// ---------------------------------------------------------------------------
// Attention kernel: EXACT R15 version (best measured: 78.8us, DRAM-bound).
// 2x2-blocked score pass + 2-output V pass.
// ---------------------------------------------------------------------------
#define HSTR 196                         // padded per-head stride (floats)
#define HSTR4 49                         // float4 stride

__global__ __launch_bounds__(256, 4) void attn_kernel(float* __restrict__ out)
{
    __shared__ __align__(16) float qkv[16 * HSTR];   // 12.25 KB
    __shared__ float E[256];
    __shared__ float invden[16];

    const int token = blockIdx.x;
    const int tid   = threadIdx.x;

    const float4* row4 = (const float4*)(g_qkv + (size_t)token * N_);
    #pragma unroll
    for (int r = 0; r < 3; r++) {
        int i = tid + r * 256;
        int head = i / 48;
        int w    = i - head * 48;
        ((float4*)qkv)[head * HSTR4 + w] = row4[i];
    }
    __syncthreads();

    if (tid < 64) {
        const int h8 = tid >> 3;         // 0..7
        const int g8 = tid & 7;          // 0..7
        const float* q0 = &qkv[h8 * HSTR];
        const float* q1 = &qkv[(h8 + 8) * HSTR];
        const float* k0 = &qkv[g8 * HSTR + 64];
        const float* k1 = &qkv[(g8 + 8) * HSTR + 64];
        float s00 = 0.f, s01 = 0.f, s10 = 0.f, s11 = 0.f;
        #pragma unroll
        for (int d = 0; d < 64; d++) {
            float qa = q0[d], qb = q1[d];
            float ka = k0[d], kb = k1[d];
            s00 = fmaf(qa, ka, s00);
            s01 = fmaf(qa, kb, s01);
            s10 = fmaf(qb, ka, s10);
            s11 = fmaf(qb, kb, s11);
        }
        s00 -= 20.0f; s01 -= 20.0f; s10 -= 20.0f; s11 -= 20.0f;
        E[h8 * 16 + g8]            = (s00 > 20.f || s00 < -20.f) ? 0.f : expf(s00);
        E[h8 * 16 + g8 + 8]        = (s01 > 20.f || s01 < -20.f) ? 0.f : expf(s01);
        E[(h8 + 8) * 16 + g8]      = (s10 > 20.f || s10 < -20.f) ? 0.f : expf(s10);
        E[(h8 + 8) * 16 + g8 + 8]  = (s11 > 20.f || s11 < -20.f) ? 0.f : expf(s11);
    }
    __syncthreads();

    if (tid < 16) {
        float den = 0.0f;
        #pragma unroll
        for (int gg = 0; gg < 16; gg++) den += E[tid * 16 + gg];
        invden[tid] = 1.0f / den;
    }
    __syncthreads();

    float* o = out + (size_t)token * 1024;
    #pragma unroll
    for (int r = 0; r < 2; r++) {
        int idx = tid + r * 256;          // 0..511
        int hh8 = idx >> 6;               // 0..7
        int d   = idx & 63;
        float a0 = 0.0f, a1 = 0.0f;
        const float* E0 = &E[hh8 * 16];
        const float* E1 = &E[(hh8 + 8) * 16];
        #pragma unroll
        for (int gg = 0; gg < 16; gg++) {
            float v = qkv[gg * HSTR + 128 + d];
            a0 = fmaf(E0[gg], v, a0);
            a1 = fmaf(E1[gg], v, a1);
        }
        o[hh8 * 64 + d]       = a0 * invden[hh8];
        o[(hh8 + 8) * 64 + d] = a1 * invden[hh8 + 8];
    }
}

// ---------------------------------------------------------------------------
extern "C" void kernel_launch(void* const* d_in, const int* in_sizes, int n_in,
                              void* d_out, int out_size)
{
    const float* x = (const float*)d_in[0];
    const float* W = (const float*)d_in[1];
    const float* b = (const float*)d_in[2];
    float* out = (float*)d_out;

    cudaFuncSetAttribute(gemm_fp16_kernel,
                         cudaFuncAttributeMaxDynamicSharedMemorySize, SMEM_TOTAL);

    split_x_kernel<<<(M_ * K_) / (256 * 4), 256>>>(x);
    split_w_kernel<<<dim3(K_ / 32, N_ / 32), 256>>>(W);
    gemm_fp16_kernel<<<dim3(N_ / 128, M_ / 128), 256, SMEM_TOTAL>>>(b);
    attn_kernel<<<M_, 256>>>(out);
}

// round 17
// speedup vs baseline: 1.2354x; 1.0173x over previous
#include <cuda_runtime.h>
#include <cuda_fp16.h>
#include <cstdint>

#define M_ 16384
#define N_ 3072
#define K_ 1024

// -------- device scratch (allowed: __device__ globals) --------
__device__ float  g_qkv[(size_t)M_ * N_];      // 192 MB
__device__ __half g_Ah[(size_t)M_ * K_];       // 32 MB  x fp16   [M,K]
__device__ __half g_Bh[(size_t)N_ * K_];       // 6 MB   W^T fp16 [N,K]

// ---------------------------------------------------------------------------
// Pre-kernel 1: convert x -> fp16, same [M,K] layout.
// ---------------------------------------------------------------------------
__global__ __launch_bounds__(256) void split_x_kernel(const float* __restrict__ x)
{
    size_t idx = (size_t)blockIdx.x * 256 + threadIdx.x;    // float4 index
    float4 v = ((const float4*)x)[idx];
    ((__half2*)g_Ah)[2 * idx]     = __halves2half2(__float2half_rn(v.x), __float2half_rn(v.y));
    ((__half2*)g_Ah)[2 * idx + 1] = __halves2half2(__float2half_rn(v.z), __float2half_rn(v.w));
}

// ---------------------------------------------------------------------------
// Pre-kernel 2: transpose W [K,N] -> g_Bh fp16 [N,K].
// ---------------------------------------------------------------------------
__global__ __launch_bounds__(256) void split_w_kernel(const float* __restrict__ W)
{
    __shared__ float t[32][33];
    const int k0 = blockIdx.x * 32;
    const int n0 = blockIdx.y * 32;
    const int tid = threadIdx.x;
    #pragma unroll
    for (int i = 0; i < 4; i++) {
        int idx = tid + i * 256;
        int r = idx >> 5, c = idx & 31;
        t[r][c] = W[(size_t)(k0 + r) * N_ + n0 + c];
    }
    __syncthreads();
    #pragma unroll
    for (int i = 0; i < 4; i++) {
        int idx = tid + i * 256;
        int r = idx >> 5, c = idx & 31;
        g_Bh[(size_t)(n0 + r) * K_ + k0 + c] = __float2half_rn(t[c][r]);
    }
}

// ---------------------------------------------------------------------------
// Main GEMM: mma.sync.m16n8k16 fp16, single pass, f32 acc. CTA 128x128,
// 8 warps (2x4), warp tile 64x32. KC=64 (16 chunks -> half the barriers of
// KC=32) with SW128 XOR swizzle on 128B rows: conflict-free ldmatrix without
// padding (integer padding cannot fix the 8-row collision; XOR can).
// 2-stage cp.async. MMA order identical to R14 -> bit-identical results.
// ---------------------------------------------------------------------------
#define KC 64
#define ROWB 128
#define TILE_BYTES (128 * ROWB)            // 16384
#define STG_BYTES (2 * TILE_BYTES)         // A, B = 32768
#define SMEM_TOTAL (2 * STG_BYTES)         // 65536

__device__ __forceinline__ uint32_t cvta_smem(const void* p) {
    uint32_t a;
    asm("{ .reg .u64 t; cvta.to.shared.u64 t, %1; cvt.u32.u64 %0, t; }"
        : "=r"(a) : "l"(p));
    return a;
}
__device__ __forceinline__ uint32_t swz(uint32_t o) {   // SW128 (tile-local)
    return o ^ ((o >> 3) & 0x70);
}

#define CP16(dst, src) \
    asm volatile("cp.async.cg.shared.global [%0], [%1], 16;" \
                 :: "r"(dst), "l"(src) : "memory")

#define LDSM4(r, addr) \
    asm volatile("ldmatrix.sync.aligned.m8n8.x4.shared.b16 {%0,%1,%2,%3}, [%4];" \
                 : "=r"((r)[0]), "=r"((r)[1]), "=r"((r)[2]), "=r"((r)[3]) \
                 : "r"(addr))

#define MMAF32(c, a, b0, b1) \
    asm volatile("mma.sync.aligned.m16n8k16.row.col.f32.f16.f16.f32 " \
                 "{%0,%1,%2,%3}, {%4,%5,%6,%7}, {%8,%9}, {%0,%1,%2,%3};" \
                 : "+f"((c)[0]), "+f"((c)[1]), "+f"((c)[2]), "+f"((c)[3]) \
                 : "r"((a)[0]), "r"((a)[1]), "r"((a)[2]), "r"((a)[3]), \
                   "r"(b0), "r"(b1))

__global__ __launch_bounds__(256) void gemm_fp16_kernel(const float* __restrict__ bias)
{
    extern __shared__ __align__(128) char smem[];
    const uint32_t sb = cvta_smem(smem);

    const int tid  = threadIdx.x;
    const int wid  = tid >> 5;
    const int lane = tid & 31;
    const int wm   = wid >> 2;          // 0..1 (M)
    const int wn   = wid & 3;           // 0..3 (N)
    const int n0 = blockIdx.x * 128;
    const int m0 = blockIdx.y * 128;

    // cp.async: 128 rows x 128B per tile; 2 threads/row, 4 swizzled CP16 each.
    const int row = tid >> 1;            // 0..127
    const int sg0 = (tid & 1) * 4;       // first 16B segment index (0 or 4)

    float acc[4][4][4];
    #pragma unroll
    for (int i = 0; i < 4; i++)
        #pragma unroll
        for (int j = 0; j < 4; j++)
            #pragma unroll
            for (int q = 0; q < 4; q++) acc[i][j][q] = 0.0f;

    #define LOAD_STAGE(s, c)  do {                                              \
        uint32_t db = sb + (s) * STG_BYTES;                                     \
        int k0 = (c) * KC;                                                      \
        const char* ga = (const char*)(g_Ah + (size_t)(m0 + row) * K_ + k0);    \
        const char* gb = (const char*)(g_Bh + (size_t)(n0 + row) * K_ + k0);    \
        _Pragma("unroll")                                                       \
        for (int i = 0; i < 4; i++) {                                           \
            uint32_t so = swz(row * ROWB + (sg0 + i) * 16);                     \
            CP16(db + so, ga + (sg0 + i) * 16);                                 \
            CP16(db + TILE_BYTES + so, gb + (sg0 + i) * 16);                    \
        }                                                                       \
        asm volatile("cp.async.commit_group;" ::: "memory");                    \
    } while (0)

    LOAD_STAGE(0, 0);

    const int rA = wm * 64 + ((lane >> 3) & 1) * 8 + (lane & 7);
    const int cA = ((lane >> 4) & 1) * 16;                 // byte col + kk*32
    const int rB = wn * 32 + ((lane >> 4) & 1) * 8 + (lane & 7);
    const int cB = ((lane >> 3) & 1) * 16;                 // byte col + kk*32

    const int NCH = K_ / KC;               // 16
    for (int c = 0; c < NCH; c++) {
        if (c + 1 < NCH) {
            LOAD_STAGE((c + 1) & 1, c + 1);
            asm volatile("cp.async.wait_group 1;" ::: "memory");
        } else {
            asm volatile("cp.async.wait_group 0;" ::: "memory");
        }
        __syncthreads();

        const uint32_t st = sb + (c & 1) * STG_BYTES;
        #pragma unroll
        for (int kk = 0; kk < 4; kk++) {
            uint32_t a_f[4][4], b_f[2][4];
            #pragma unroll
            for (int mi = 0; mi < 4; mi++) {
                uint32_t ad = st + swz((rA + mi * 16) * ROWB + cA + kk * 32);
                LDSM4(a_f[mi], ad);
            }
            #pragma unroll
            for (int ni = 0; ni < 2; ni++) {
                uint32_t bd = st + TILE_BYTES +
                              swz((rB + ni * 16) * ROWB + cB + kk * 32);
                LDSM4(b_f[ni], bd);
            }
            #pragma unroll
            for (int mi = 0; mi < 4; mi++)
                #pragma unroll
                for (int nj = 0; nj < 4; nj++)
                    MMAF32(acc[mi][nj], a_f[mi],
                           b_f[nj >> 1][(nj & 1) * 2], b_f[nj >> 1][(nj & 1) * 2 + 1]);
        }
        __syncthreads();
    }

    // ---- epilogue: bias + store f32 ----
    #pragma unroll
    for (int mi = 0; mi < 4; mi++) {
        #pragma unroll
        for (int nj = 0; nj < 4; nj++) {
            int orow = m0 + wm * 64 + mi * 16 + (lane >> 2);
            int ocol = n0 + wn * 32 + nj * 8 + (lane & 3) * 2;
            float2 bv = *(const float2*)(bias + ocol);
            float2 v0, v1;
            v0.x = acc[mi][nj][0] + bv.x;
            v0.y = acc[mi][nj][1] + bv.y;
            v1.x = acc[mi][nj][2] + bv.x;
            v1.y = acc[mi][nj][3] + bv.y;
            *(float2*)(g_qkv + (size_t)orow * N_ + ocol)       = v0;
            *(float2*)(g_qkv + (size_t)(orow + 8) * N_ + ocol) = v1;
        }
    }
}

// ---------------------------------------------------------------------------
// Attention kernel: TWO tokens per block (grid 8192). Doubles staging MLP
// (6 float4/thread), score pass uses 128 threads, halves per-token barrier
// cost. Per-token math identical to R15/R16 -> bit-identical output.
// ---------------------------------------------------------------------------
#define HSTR 196                         // padded per-head stride (floats)
#define HSTR4 49                         // float4 stride

__global__ __launch_bounds__(256, 4) void attn_kernel(float* __restrict__ out)
{
    __shared__ __align__(16) float qkv[2][16 * HSTR];   // 24.5 KB
    __shared__ float E[2][256];
    __shared__ float invden[2][16];

    const int token0 = blockIdx.x * 2;
    const int tid    = threadIdx.x;

    // Stage two token rows (2 x 768 float4) into padded layout.
    #pragma unroll
    for (int r = 0; r < 6; r++) {
        int i = tid + r * 256;            // 0..1535
        int t = (i >= 768);
        int ii = i - t * 768;
        int head = ii / 48;
        int w    = ii - head * 48;
        ((float4*)qkv[t])[head * HSTR4 + w] =
            ((const float4*)(g_qkv + (size_t)(token0 + t) * N_))[ii];
    }
    __syncthreads();

    // Scores: 128 threads; thread -> (token, 2x2 block of (h,g)).
    if (tid < 128) {
        const int t  = tid >> 6;
        const int lt = tid & 63;
        const int h8 = lt >> 3;
        const int g8 = lt & 7;
        const float* q0 = &qkv[t][h8 * HSTR];
        const float* q1 = &qkv[t][(h8 + 8) * HSTR];
        const float* k0 = &qkv[t][g8 * HSTR + 64];
        const float* k1 = &qkv[t][(g8 + 8) * HSTR + 64];
        float s00 = 0.f, s01 = 0.f, s10 = 0.f, s11 = 0.f;
        #pragma unroll
        for (int d = 0; d < 64; d++) {
            float qa = q0[d], qb = q1[d];
            float ka = k0[d], kb = k1[d];
            s00 = fmaf(qa, ka, s00);
            s01 = fmaf(qa, kb, s01);
            s10 = fmaf(qb, ka, s10);
            s11 = fmaf(qb, kb, s11);
        }
        s00 -= 20.0f; s01 -= 20.0f; s10 -= 20.0f; s11 -= 20.0f;
        E[t][h8 * 16 + g8]           = (s00 > 20.f || s00 < -20.f) ? 0.f : expf(s00);
        E[t][h8 * 16 + g8 + 8]       = (s01 > 20.f || s01 < -20.f) ? 0.f : expf(s01);
        E[t][(h8 + 8) * 16 + g8]     = (s10 > 20.f || s10 < -20.f) ? 0.f : expf(s10);
        E[t][(h8 + 8) * 16 + g8 + 8] = (s11 > 20.f || s11 < -20.f) ? 0.f : expf(s11);
    }
    __syncthreads();

    if (tid < 32) {
        const int t = tid >> 4;
        const int h = tid & 15;
        float den = 0.0f;
        #pragma unroll
        for (int gg = 0; gg < 16; gg++) den += E[t][h * 16 + gg];
        invden[t][h] = 1.0f / den;
    }
    __syncthreads();

    // V pass: 4 rounds; thread -> (token, hh8 pair, d), shared V loads.
    #pragma unroll
    for (int r = 0; r < 4; r++) {
        int idx  = tid + r * 256;         // 0..1023
        int t    = idx >> 9;
        int lidx = idx & 511;
        int hh8  = lidx >> 6;             // 0..7
        int d    = lidx & 63;
        float a0 = 0.0f, a1 = 0.0f;
        const float* E0 = &E[t][hh8 * 16];
        const float* E1 = &E[t][(hh8 + 8) * 16];
        #pragma unroll
        for (int gg = 0; gg < 16; gg++) {
            float v = qkv[t][gg * HSTR + 128 + d];
            a0 = fmaf(E0[gg], v, a0);
            a1 = fmaf(E1[gg], v, a1);
        }
        float* o = out + (size_t)(token0 + t) * 1024;
        o[hh8 * 64 + d]       = a0 * invden[t][hh8];
        o[(hh8 + 8) * 64 + d] = a1 * invden[t][hh8 + 8];
    }
}

// ---------------------------------------------------------------------------
extern "C" void kernel_launch(void* const* d_in, const int* in_sizes, int n_in,
                              void* d_out, int out_size)
{
    const float* x = (const float*)d_in[0];
    const float* W = (const float*)d_in[1];
    const float* b = (const float*)d_in[2];
    float* out = (float*)d_out;

    cudaFuncSetAttribute(gemm_fp16_kernel,
                         cudaFuncAttributeMaxDynamicSharedMemorySize, SMEM_TOTAL);

    split_x_kernel<<<(M_ * K_) / (256 * 4), 256>>>(x);
    split_w_kernel<<<dim3(K_ / 32, N_ / 32), 256>>>(W);
    gemm_fp16_kernel<<<dim3(N_ / 128, M_ / 128), 256, SMEM_TOTAL>>>(b);
    attn_kernel<<<M_ / 2, 256>>>(out);
}